// round 15
// baseline (speedup 1.0000x reference)
#include <cuda_runtime.h>

#define THREADS 256
#define NWARP   (THREADS / 32)
#define NSUM    11
#define BATCH   8
#define MAXB    4096
#define GROUP   32

// Per-row folded DP sums, transposed [sum][row]; per-group completion counters.
__device__ double g_dscratch[NSUM * MAXB];
__device__ int    g_count[MAXB / GROUP];

__device__ __forceinline__ float ex2_approx(float t) {
    float r; asm("ex2.approx.f32 %0, %1;" : "=f"(r) : "f"(t)); return r;
}
__device__ __forceinline__ float rcp_approx(float t) {
    float r; asm("rcp.approx.f32 %0, %1;" : "=f"(r) : "f"(t)); return r;
}
// acc = v*1.0 + acc — bit-identical to acc += v; FFMA-imm form (rt_SMSP=1).
__device__ __forceinline__ void fadd_imm(float& acc, float v) {
    asm("fma.rn.f32 %0, %1, 0f3F800000, %0;" : "+f"(acc) : "f"(v));
}
// Branchless DP reciprocal: fp32 rcp seed + 2 Newton steps (DFMA only).
__device__ __forceinline__ double drcp(double d) {
    double r = (double)rcp_approx((float)d);
    double e = fma(-d, r, 1.0);
    r = fma(r, e, r);
    e = fma(-d, r, 1.0);
    r = fma(r, e, r);
    return r;
}

// ===== EXACT frozen fp32 element values =====
//  0: s        1: s^2
//  2: sp       3: sp*x      4: sp*x^2
//  5: s*sp     6: s*sp*x    7: s*sp*x^2
//  8: s^2*sp   9: s^2*sp*x 10: s^2*sp*x^2
#define ELEM_BODY(xv)                                               \
    do {                                                            \
        float _x   = (xv);                                          \
        float _t   = fmaf(c1, _x, c2);      /* -u*log2e */          \
        float _e   = ex2_approx(_t);        /* exp(-u)  */          \
        float _s   = rcp_approx(1.0f + _e); /* sigmoid  */          \
        float _sp  = fmaf(-_s, _s, _s);     /* s(1-s)   */          \
        float _ssp = _s * _sp;                                      \
        float _s2sp= _s * _ssp;                                     \
        float _x2  = _x * _x;                                       \
        fadd_imm(acc0, _s);                                         \
        acc1   = fmaf(_s, _s, acc1);                                \
        fadd_imm(acc2, _sp);                                        \
        acc3   = fmaf(_sp, _x, acc3);                               \
        acc4   = fmaf(_sp, _x2, acc4);                              \
        fadd_imm(acc5, _ssp);                                       \
        acc6   = fmaf(_ssp, _x, acc6);                              \
        acc7   = fmaf(_ssp, _x2, acc7);                             \
        fadd_imm(acc8, _s2sp);                                      \
        acc9   = fmaf(_s2sp, _x, acc9);                             \
        acc10  = fmaf(_s2sp, _x2, acc10);                           \
    } while (0)

// DP epilogue for one row from folded sums (identical formulas; DP-domain).
__device__ __noinline__ void solve_row(int row, const float* __restrict__ mean,
                                       const float* __restrict__ var,
                                       float* __restrict__ out, int B, int N)
{
    double S[NSUM];
#pragma unroll
    for (int k = 0; k < NSUM; ++k) S[k] = g_dscratch[(size_t)k * MAXB + row];

    const double invN = 1.0 / (double)N;
    const double fm     = S[0]  * invN;
    const double ms2    = S[1]  * invN;
    const double msp0   = S[2]  * invN;
    const double msp1   = S[3]  * invN;
    const double msp2   = S[4]  * invN;
    const double mssp0  = S[5]  * invN;
    const double mssp1  = S[6]  * invN;
    const double mssp2  = S[7]  * invN;
    const double ms2sp0 = S[8]  * invN;
    const double ms2sp1 = S[9]  * invN;
    const double ms2sp2 = S[10] * invN;

    const double dem_db   = msp0;
    const double dem_da   = msp1;
    const double d2em_db2 = msp0 - 2.0 * mssp0;
    const double d2em_dab = msp1 - 2.0 * mssp1;
    const double d2em_da2 = msp2 - 2.0 * mssp2;
    const double mg   = 2.0 * mssp0 - 3.0 * ms2sp0;
    const double mgx  = 2.0 * mssp1 - 3.0 * ms2sp1;
    const double mgx2 = 2.0 * mssp2 - 3.0 * ms2sp2;

    const double em = fm - (double)__ldg(mean + row);
    const double ev = ms2 - fm * fm - (double)__ldg(var + row);

    const double dev_da   = 2.0 * (mssp1 - fm * dem_da);
    const double dev_db   = 2.0 * (mssp0 - fm * dem_db);
    const double d2ev_da2 = 2.0 * (mgx2 - dem_da * dem_da - fm * d2em_da2);
    const double d2ev_dab = 2.0 * (mgx  - dem_da * dem_db - fm * d2em_dab);
    const double d2ev_db2 = 2.0 * (mg   - dem_db * dem_db - fm * d2em_db2);

    const double dl_da = 2.0 * (em * dem_da + ev * dev_da);
    const double dl_db = 2.0 * (em * dem_db + ev * dev_db);

    const double d2l_da2 = 2.0 * (dem_da * dem_da + em * d2em_da2 +
                                  dev_da * dev_da + ev * d2ev_da2);
    const double d2l_dab = 2.0 * (dem_da * dem_db + em * d2em_dab +
                                  dev_da * dev_db + ev * d2ev_dab);
    const double d2l_db2 = 2.0 * (dem_db * dem_db + em * d2em_db2 +
                                  dev_db * dev_db + ev * d2ev_db2);

    const double den = d2l_da2 * d2l_db2 - d2l_dab * d2l_dab;
    const double inv = drcp(den);
    const double na  = (dl_da * d2l_db2 - dl_db * d2l_dab) * inv;
    const double nb  = (dl_db * d2l_da2 - dl_da * d2l_dab) * inv;

    out[row]     = (float)na;
    out[row + B] = (float)nb;
}

__global__ __launch_bounds__(THREADS, 6) void nsab_kernel(
    const float* __restrict__ x, const float* __restrict__ a,
    const float* __restrict__ b, const float* __restrict__ mean,
    const float* __restrict__ var, float* __restrict__ out,
    int B, int N)
{
    const int row = blockIdx.x;
    const int tid = threadIdx.x;

    const float* xrow = x + (size_t)row * (size_t)N;
    const float LOG2E = 1.4426950408889634f;
    const float c1 = -__ldg(a + row) * LOG2E;
    const float c2 = -__ldg(b + row) * LOG2E;

    float acc0 = 0.f, acc1 = 0.f, acc2 = 0.f, acc3 = 0.f, acc4 = 0.f,
          acc5 = 0.f, acc6 = 0.f, acc7 = 0.f, acc8 = 0.f, acc9 = 0.f,
          acc10 = 0.f;

    const int n4 = N >> 2;
    const float4* __restrict__ x4 = (const float4*)xrow;

    // Main loop: BATCH front-issued float4 loads; frozen element order.
    int i = tid;
    for (; i + (BATCH - 1) * THREADS < n4; i += BATCH * THREADS) {
        float4 v[BATCH];
#pragma unroll
        for (int j = 0; j < BATCH; ++j) v[j] = x4[i + j * THREADS];
#pragma unroll
        for (int j = 0; j < BATCH; ++j) {
            ELEM_BODY(v[j].x);
            ELEM_BODY(v[j].y);
            ELEM_BODY(v[j].z);
            ELEM_BODY(v[j].w);
        }
    }
    for (; i < n4; i += THREADS) {
        float4 v = x4[i];
        ELEM_BODY(v.x);
        ELEM_BODY(v.y);
        ELEM_BODY(v.z);
        ELEM_BODY(v.w);
    }
    for (int k = (n4 << 2) + tid; k < N; k += THREADS) {
        ELEM_BODY(xrow[k]);
    }

    float sums[NSUM] = {acc0, acc1, acc2, acc3, acc4, acc5,
                        acc6, acc7, acc8, acc9, acc10};

    // fp32 warp tree reduce — frozen.
#pragma unroll
    for (int k = 0; k < NSUM; ++k) {
#pragma unroll
        for (int o = 16; o > 0; o >>= 1)
            sums[k] += __shfl_xor_sync(0xffffffffu, sums[k], o);
    }

    __shared__ float red[NWARP][NSUM];
    const int wid  = tid >> 5;
    const int lane = tid & 31;
    if (lane == 0) {
#pragma unroll
        for (int k = 0; k < NSUM; ++k) red[wid][k] = sums[k];
    }
    __syncthreads();

    // Warps 1-7 are done after the barrier; warp 0 publishes + maybe solves.
    if (wid != 0) return;

    // Threads 0..10: pairwise DP fold (frozen order) -> transposed scratch.
    if (tid < NSUM) {
        const int k = tid;
        double t01 = (double)red[0][k] + (double)red[1][k];
        double t23 = (double)red[2][k] + (double)red[3][k];
        double t45 = (double)red[4][k] + (double)red[5][k];
        double t67 = (double)red[6][k] + (double)red[7][k];
        g_dscratch[(size_t)k * MAXB + row] = (t01 + t23) + (t45 + t67);
        __threadfence();   // release this row's doubles
    }
    __syncwarp();

    // Last CTA of the 32-row group solves the whole group, 1 row/lane.
    const int group = row / GROUP;
    int is_last = 0;
    if (lane == 0) {
        int prev = atomicAdd(&g_count[group], 1);
        is_last = (prev == GROUP - 1);
    }
    is_last = __shfl_sync(0xffffffffu, is_last, 0);
    if (!is_last) return;

    __threadfence();   // acquire: all 32 rows' scratch visible

    const int srow = group * GROUP + lane;
    if (srow < B) solve_row(srow, mean, var, out, B, N);
}

extern "C" void kernel_launch(void* const* d_in, const int* in_sizes, int n_in,
                              void* d_out, int out_size)
{
    const float* x    = (const float*)d_in[0];
    const float* a    = (const float*)d_in[1];
    const float* b    = (const float*)d_in[2];
    const float* mean = (const float*)d_in[3];
    const float* var  = (const float*)d_in[4];
    // d_in[5] = dim (always 1) — ignored.

    const int B = in_sizes[1];
    const int N = in_sizes[0] / B;

    // Reset per-group counters each call (graph-capturable async memset).
    void* cnt_ptr = nullptr;
    cudaGetSymbolAddress(&cnt_ptr, g_count);
    cudaMemsetAsync(cnt_ptr, 0, sizeof(int) * ((B + GROUP - 1) / GROUP), 0);

    nsab_kernel<<<B, THREADS>>>(x, a, b, mean, var, (float*)d_out, B, N);
}

// round 16
// speedup vs baseline: 1.1131x; 1.1131x over previous
#include <cuda_runtime.h>

#define THREADS 256
#define NWARP   (THREADS / 32)
#define NSUM    11
#define BATCH   8
#define MAXB    4096

// Per-row folded DP sums, transposed [sum][row] for coalesced solve loads.
__device__ double g_dscratch[NSUM * MAXB];

__device__ __forceinline__ float ex2_approx(float t) {
    float r; asm("ex2.approx.f32 %0, %1;" : "=f"(r) : "f"(t)); return r;
}
__device__ __forceinline__ float rcp_approx(float t) {
    float r; asm("rcp.approx.f32 %0, %1;" : "=f"(r) : "f"(t)); return r;
}
// acc = v*1.0 + acc — bit-identical to acc += v; FFMA-imm form (rt_SMSP=1).
__device__ __forceinline__ void fadd_imm(float& acc, float v) {
    asm("fma.rn.f32 %0, %1, 0f3F800000, %0;" : "+f"(acc) : "f"(v));
}
// Branchless DP reciprocal: fp32 rcp seed + 2 Newton steps (DFMA only).
__device__ __forceinline__ double drcp(double d) {
    double r = (double)rcp_approx((float)d);
    double e = fma(-d, r, 1.0);
    r = fma(r, e, r);
    e = fma(-d, r, 1.0);
    r = fma(r, e, r);
    return r;
}

// ===== EXACT frozen fp32 element values =====
//  0: s        1: s^2
//  2: sp       3: sp*x      4: sp*x^2
//  5: s*sp     6: s*sp*x    7: s*sp*x^2
//  8: s^2*sp   9: s^2*sp*x 10: s^2*sp*x^2
#define ELEM_BODY(xv)                                               \
    do {                                                            \
        float _x   = (xv);                                          \
        float _t   = fmaf(c1, _x, c2);      /* -u*log2e */          \
        float _e   = ex2_approx(_t);        /* exp(-u)  */          \
        float _s   = rcp_approx(1.0f + _e); /* sigmoid  */          \
        float _sp  = fmaf(-_s, _s, _s);     /* s(1-s)   */          \
        float _ssp = _s * _sp;                                      \
        float _s2sp= _s * _ssp;                                     \
        float _x2  = _x * _x;                                       \
        fadd_imm(acc0, _s);                                         \
        acc1   = fmaf(_s, _s, acc1);                                \
        fadd_imm(acc2, _sp);                                        \
        acc3   = fmaf(_sp, _x, acc3);                               \
        acc4   = fmaf(_sp, _x2, acc4);                              \
        fadd_imm(acc5, _ssp);                                       \
        acc6   = fmaf(_ssp, _x, acc6);                              \
        acc7   = fmaf(_ssp, _x2, acc7);                             \
        fadd_imm(acc8, _s2sp);                                      \
        acc9   = fmaf(_s2sp, _x, acc9);                             \
        acc10  = fmaf(_s2sp, _x2, acc10);                           \
    } while (0)

__global__ __launch_bounds__(THREADS) void nsab_reduce_kernel(
    const float* __restrict__ x, const float* __restrict__ a,
    const float* __restrict__ b, int N)
{
    const int row = blockIdx.x;
    const int tid = threadIdx.x;

    const float* xrow = x + (size_t)row * (size_t)N;
    const float LOG2E = 1.4426950408889634f;
    const float c1 = -__ldg(a + row) * LOG2E;
    const float c2 = -__ldg(b + row) * LOG2E;

    float acc0 = 0.f, acc1 = 0.f, acc2 = 0.f, acc3 = 0.f, acc4 = 0.f,
          acc5 = 0.f, acc6 = 0.f, acc7 = 0.f, acc8 = 0.f, acc9 = 0.f,
          acc10 = 0.f;

    const int n4 = N >> 2;
    const float4* __restrict__ x4 = (const float4*)xrow;

    // Main loop: BATCH front-issued float4 loads; per-thread element order is
    // identical to the simple strided loop (numerics frozen). For N=8192,
    // THREADS=256, BATCH=8 this is exactly one iteration (full MLP).
    int i = tid;
    for (; i + (BATCH - 1) * THREADS < n4; i += BATCH * THREADS) {
        float4 v[BATCH];
#pragma unroll
        for (int j = 0; j < BATCH; ++j) v[j] = x4[i + j * THREADS];
#pragma unroll
        for (int j = 0; j < BATCH; ++j) {
            ELEM_BODY(v[j].x);
            ELEM_BODY(v[j].y);
            ELEM_BODY(v[j].z);
            ELEM_BODY(v[j].w);
        }
    }
    // Remainder float4s (unused for N=8192).
    for (; i < n4; i += THREADS) {
        float4 v = x4[i];
        ELEM_BODY(v.x);
        ELEM_BODY(v.y);
        ELEM_BODY(v.z);
        ELEM_BODY(v.w);
    }
    // Scalar tail (N % 4 != 0; unused for N=8192).
    for (int k = (n4 << 2) + tid; k < N; k += THREADS) {
        ELEM_BODY(xrow[k]);
    }

    float sums[NSUM] = {acc0, acc1, acc2, acc3, acc4, acc5,
                        acc6, acc7, acc8, acc9, acc10};

    // fp32 warp tree reduce — frozen.
#pragma unroll
    for (int k = 0; k < NSUM; ++k) {
#pragma unroll
        for (int o = 16; o > 0; o >>= 1)
            sums[k] += __shfl_xor_sync(0xffffffffu, sums[k], o);
    }

    __shared__ float red[NWARP][NSUM];
    const int wid  = tid >> 5;
    const int lane = tid & 31;
    if (lane == 0) {
#pragma unroll
        for (int k = 0; k < NSUM; ++k) red[wid][k] = sums[k];
    }
    __syncthreads();

    // Threads 0..10: pairwise DP fold (frozen order) -> transposed scratch.
    if (tid < NSUM) {
        const int k = tid;
        double t01 = (double)red[0][k] + (double)red[1][k];
        double t23 = (double)red[2][k] + (double)red[3][k];
        double t45 = (double)red[4][k] + (double)red[5][k];
        double t67 = (double)red[6][k] + (double)red[7][k];
        g_dscratch[(size_t)k * MAXB + row] = (t01 + t23) + (t45 + t67);
    }
}

// One thread per row: 11 coalesced double loads + slim branchless DP epilogue.
// __launch_bounds__(32, 1): block=32 makes occupancy irrelevant, so give
// ptxas full register freedom — the epilogue needs ~25 live doubles; at the
// previous 39-reg budget it spilled and serialized every DP op at full
// latency (~78 cyc/op measured). With headroom, independent DFMAs overlap.
__global__ __launch_bounds__(32, 1) void nsab_solve_kernel(
    const float* __restrict__ mean, const float* __restrict__ var,
    float* __restrict__ out, int B, int N)
{
    const int row = blockIdx.x * 32 + threadIdx.x;
    if (row >= B) return;

    double S[NSUM];
#pragma unroll
    for (int k = 0; k < NSUM; ++k) S[k] = g_dscratch[(size_t)k * MAXB + row];

    const double invN = 1.0 / (double)N;
    const double fm     = S[0]  * invN;   // m(f)
    const double ms2    = S[1]  * invN;   // m(f^2)
    const double msp0   = S[2]  * invN;   // m(sp)
    const double msp1   = S[3]  * invN;   // m(sp x)
    const double msp2   = S[4]  * invN;   // m(sp x^2)
    const double mssp0  = S[5]  * invN;   // m(s sp)
    const double mssp1  = S[6]  * invN;   // m(s sp x)
    const double mssp2  = S[7]  * invN;   // m(s sp x^2)
    const double ms2sp0 = S[8]  * invN;   // m(s^2 sp)
    const double ms2sp1 = S[9]  * invN;   // m(s^2 sp x)
    const double ms2sp2 = S[10] * invN;   // m(s^2 sp x^2)

    const double dem_db   = msp0;
    const double dem_da   = msp1;
    const double d2em_db2 = msp0 - 2.0 * mssp0;   // m(spp)
    const double d2em_dab = msp1 - 2.0 * mssp1;   // m(spp x)
    const double d2em_da2 = msp2 - 2.0 * mssp2;   // m(spp x^2)
    const double mg   = 2.0 * mssp0 - 3.0 * ms2sp0;  // m(sp^2 + f spp)
    const double mgx  = 2.0 * mssp1 - 3.0 * ms2sp1;
    const double mgx2 = 2.0 * mssp2 - 3.0 * ms2sp2;

    const double em = fm - (double)__ldg(mean + row);
    const double ev = ms2 - fm * fm - (double)__ldg(var + row);

    const double dev_da   = 2.0 * (mssp1 - fm * dem_da);
    const double dev_db   = 2.0 * (mssp0 - fm * dem_db);
    const double d2ev_da2 = 2.0 * (mgx2 - dem_da * dem_da - fm * d2em_da2);
    const double d2ev_dab = 2.0 * (mgx  - dem_da * dem_db - fm * d2em_dab);
    const double d2ev_db2 = 2.0 * (mg   - dem_db * dem_db - fm * d2em_db2);

    const double dl_da = 2.0 * (em * dem_da + ev * dev_da);
    const double dl_db = 2.0 * (em * dem_db + ev * dev_db);

    const double d2l_da2 = 2.0 * (dem_da * dem_da + em * d2em_da2 +
                                  dev_da * dev_da + ev * d2ev_da2);
    const double d2l_dab = 2.0 * (dem_da * dem_db + em * d2em_dab +
                                  dev_da * dev_db + ev * d2ev_dab);
    const double d2l_db2 = 2.0 * (dem_db * dem_db + em * d2em_db2 +
                                  dev_db * dev_db + ev * d2ev_db2);

    const double den = d2l_da2 * d2l_db2 - d2l_dab * d2l_dab;
    const double inv = drcp(den);
    const double na  = (dl_da * d2l_db2 - dl_db * d2l_dab) * inv;
    const double nb  = (dl_db * d2l_da2 - dl_da * d2l_dab) * inv;

    out[row]     = (float)na;
    out[row + B] = (float)nb;
}

extern "C" void kernel_launch(void* const* d_in, const int* in_sizes, int n_in,
                              void* d_out, int out_size)
{
    const float* x    = (const float*)d_in[0];
    const float* a    = (const float*)d_in[1];
    const float* b    = (const float*)d_in[2];
    const float* mean = (const float*)d_in[3];
    const float* var  = (const float*)d_in[4];
    // d_in[5] = dim (always 1) — ignored.

    const int B = in_sizes[1];
    const int N = in_sizes[0] / B;

    nsab_reduce_kernel<<<B, THREADS>>>(x, a, b, N);
    nsab_solve_kernel<<<(B + 31) / 32, 32>>>(mean, var, (float*)d_out, B, N);
}

// round 17
// speedup vs baseline: 1.1317x; 1.0168x over previous
#include <cuda_runtime.h>

#define THREADS 256
#define NWARP   (THREADS / 32)
#define NSUM    11
#define BATCH   8
#define MAXB    4096

// Per-row folded DP sums, transposed [sum][row] for coalesced solve loads.
__device__ double g_dscratch[NSUM * MAXB];

__device__ __forceinline__ float ex2_approx(float t) {
    float r; asm("ex2.approx.f32 %0, %1;" : "=f"(r) : "f"(t)); return r;
}
__device__ __forceinline__ float rcp_approx(float t) {
    float r; asm("rcp.approx.f32 %0, %1;" : "=f"(r) : "f"(t)); return r;
}
// acc = v*1.0 + acc — bit-identical to acc += v; FFMA-imm form (rt_SMSP=1).
__device__ __forceinline__ void fadd_imm(float& acc, float v) {
    asm("fma.rn.f32 %0, %1, 0f3F800000, %0;" : "+f"(acc) : "f"(v));
}
// Branchless DP reciprocal: fp32 rcp seed + 2 Newton steps (DFMA only).
__device__ __forceinline__ double drcp(double d) {
    double r = (double)rcp_approx((float)d);
    double e = fma(-d, r, 1.0);
    r = fma(r, e, r);
    e = fma(-d, r, 1.0);
    r = fma(r, e, r);
    return r;
}

// ===== EXACT frozen fp32 element values =====
//  0: s        1: s^2
//  2: sp       3: sp*x      4: sp*x^2
//  5: s*sp     6: s*sp*x    7: s*sp*x^2
//  8: s^2*sp   9: s^2*sp*x 10: s^2*sp*x^2
#define ELEM_BODY(xv)                                               \
    do {                                                            \
        float _x   = (xv);                                          \
        float _t   = fmaf(c1, _x, c2);      /* -u*log2e */          \
        float _e   = ex2_approx(_t);        /* exp(-u)  */          \
        float _s   = rcp_approx(1.0f + _e); /* sigmoid  */          \
        float _sp  = fmaf(-_s, _s, _s);     /* s(1-s)   */          \
        float _ssp = _s * _sp;                                      \
        float _s2sp= _s * _ssp;                                     \
        float _x2  = _x * _x;                                       \
        fadd_imm(acc0, _s);                                         \
        acc1   = fmaf(_s, _s, acc1);                                \
        fadd_imm(acc2, _sp);                                        \
        acc3   = fmaf(_sp, _x, acc3);                               \
        acc4   = fmaf(_sp, _x2, acc4);                              \
        fadd_imm(acc5, _ssp);                                       \
        acc6   = fmaf(_ssp, _x, acc6);                              \
        acc7   = fmaf(_ssp, _x2, acc7);                             \
        fadd_imm(acc8, _s2sp);                                      \
        acc9   = fmaf(_s2sp, _x, acc9);                             \
        acc10  = fmaf(_s2sp, _x2, acc10);                           \
    } while (0)

__global__ __launch_bounds__(THREADS) void nsab_reduce_kernel(
    const float* __restrict__ x, const float* __restrict__ a,
    const float* __restrict__ b, int N)
{
    const int row = blockIdx.x;
    const int tid = threadIdx.x;

    const float* xrow = x + (size_t)row * (size_t)N;
    const float LOG2E = 1.4426950408889634f;
    const float c1 = -__ldg(a + row) * LOG2E;
    const float c2 = -__ldg(b + row) * LOG2E;

    float acc0 = 0.f, acc1 = 0.f, acc2 = 0.f, acc3 = 0.f, acc4 = 0.f,
          acc5 = 0.f, acc6 = 0.f, acc7 = 0.f, acc8 = 0.f, acc9 = 0.f,
          acc10 = 0.f;

    const int n4 = N >> 2;
    const float4* __restrict__ x4 = (const float4*)xrow;

    // Main loop: BATCH front-issued float4 loads; frozen element order.
    int i = tid;
    for (; i + (BATCH - 1) * THREADS < n4; i += BATCH * THREADS) {
        float4 v[BATCH];
#pragma unroll
        for (int j = 0; j < BATCH; ++j) v[j] = x4[i + j * THREADS];
#pragma unroll
        for (int j = 0; j < BATCH; ++j) {
            ELEM_BODY(v[j].x);
            ELEM_BODY(v[j].y);
            ELEM_BODY(v[j].z);
            ELEM_BODY(v[j].w);
        }
    }
    for (; i < n4; i += THREADS) {
        float4 v = x4[i];
        ELEM_BODY(v.x);
        ELEM_BODY(v.y);
        ELEM_BODY(v.z);
        ELEM_BODY(v.w);
    }
    for (int k = (n4 << 2) + tid; k < N; k += THREADS) {
        ELEM_BODY(xrow[k]);
    }

    float sums[NSUM] = {acc0, acc1, acc2, acc3, acc4, acc5,
                        acc6, acc7, acc8, acc9, acc10};

    // fp32 warp tree reduce — frozen.
#pragma unroll
    for (int k = 0; k < NSUM; ++k) {
#pragma unroll
        for (int o = 16; o > 0; o >>= 1)
            sums[k] += __shfl_xor_sync(0xffffffffu, sums[k], o);
    }

    __shared__ float red[NWARP][NSUM];
    const int wid  = tid >> 5;
    const int lane = tid & 31;
    if (lane == 0) {
#pragma unroll
        for (int k = 0; k < NSUM; ++k) red[wid][k] = sums[k];
    }
    __syncthreads();

    // Threads 0..10: pairwise DP fold (frozen order) -> transposed scratch.
    if (tid < NSUM) {
        const int k = tid;
        double t01 = (double)red[0][k] + (double)red[1][k];
        double t23 = (double)red[2][k] + (double)red[3][k];
        double t45 = (double)red[4][k] + (double)red[5][k];
        double t67 = (double)red[6][k] + (double)red[7][k];
        g_dscratch[(size_t)k * MAXB + row] = (t01 + t23) + (t45 + t67);
    }
}

// TWO lanes per row: lane h=0 computes the a-side chain, h=1 the b-side.
// Shared/cross doubles are computed by BOTH lanes with identical expressions
// on identical inputs (bit-identical); 3 shfl exchanges move side values.
// Every double equals the serial version's bits exactly.
__global__ __launch_bounds__(64) void nsab_solve_kernel(
    const float* __restrict__ mean, const float* __restrict__ var,
    float* __restrict__ out, int B, int N)
{
    const int idx   = blockIdx.x * 64 + threadIdx.x;
    const int row_r = idx >> 1;               // real row
    const int h     = idx & 1;                // 0 = a-side, 1 = b-side
    const bool live = (row_r < B);
    const int row   = live ? row_r : (B - 1); // clamp: keep all lanes active

    double S[NSUM];
#pragma unroll
    for (int k = 0; k < NSUM; ++k) S[k] = g_dscratch[(size_t)k * MAXB + row];

    const double invN = 1.0 / (double)N;
    const double fm     = S[0]  * invN;
    const double ms2    = S[1]  * invN;
    const double msp0   = S[2]  * invN;
    const double msp1   = S[3]  * invN;
    const double msp2   = S[4]  * invN;
    const double mssp0  = S[5]  * invN;
    const double mssp1  = S[6]  * invN;
    const double mssp2  = S[7]  * invN;
    const double ms2sp0 = S[8]  * invN;
    const double ms2sp1 = S[9]  * invN;
    const double ms2sp2 = S[10] * invN;

    // Shared (both lanes, identical bits).
    const double dem_db   = msp0;
    const double dem_da   = msp1;
    const double d2em_dab = msp1 - 2.0 * mssp1;
    const double mgx      = 2.0 * mssp1 - 3.0 * ms2sp1;

    const double em = fm - (double)__ldg(mean + row);
    const double ev = ms2 - fm * fm - (double)__ldg(var + row);

    const double d2ev_dab = 2.0 * (mgx - dem_da * dem_db - fm * d2em_dab);

    // Side-specific chain (h=0: a-side, h=1: b-side). Expressions identical
    // to the serial version for the respective side.
    double dem_h, d2em_h, dev_h, d2ev_h;
    if (h == 0) {
        const double d2em_da2 = msp2 - 2.0 * mssp2;
        const double mgx2     = 2.0 * mssp2 - 3.0 * ms2sp2;
        dem_h  = dem_da;
        d2em_h = d2em_da2;
        dev_h  = 2.0 * (mssp1 - fm * dem_da);
        d2ev_h = 2.0 * (mgx2 - dem_da * dem_da - fm * d2em_da2);
    } else {
        const double d2em_db2 = msp0 - 2.0 * mssp0;
        const double mg       = 2.0 * mssp0 - 3.0 * ms2sp0;
        dem_h  = dem_db;
        d2em_h = d2em_db2;
        dev_h  = 2.0 * (mssp0 - fm * dem_db);
        d2ev_h = 2.0 * (mg - dem_db * dem_db - fm * d2em_db2);
    }

    const double dl_h  = 2.0 * (em * dem_h + ev * dev_h);
    const double d2l_h = 2.0 * (dem_h * dem_h + em * d2em_h +
                                dev_h * dev_h + ev * d2ev_h);

    // Exchange side values with the partner lane (adjacent lane, xor 1).
    const double dev_o = __shfl_xor_sync(0xffffffffu, dev_h, 1);
    const double dl_o  = __shfl_xor_sync(0xffffffffu, dl_h, 1);
    const double d2l_o = __shfl_xor_sync(0xffffffffu, d2l_h, 1);

    // Cross Hessian term — commutative products give identical bits on both
    // lanes (lane0: dev_h=dev_da, dev_o=dev_db; lane1 swapped).
    const double d2l_dab = 2.0 * (dem_da * dem_db + em * d2em_dab +
                                  dev_h * dev_o + ev * d2ev_dab);

    // den identical on both lanes (d2l_h*d2l_o commutative).
    const double den = d2l_h * d2l_o - d2l_dab * d2l_dab;
    const double inv = drcp(den);

    // Lane0: na = (dl_da*d2l_db2 - dl_db*d2l_dab)*inv  (own=da, other=db)
    // Lane1: nb = (dl_db*d2l_da2 - dl_da*d2l_dab)*inv  (own=db, other=da)
    const double n_h = (dl_h * d2l_o - dl_o * d2l_dab) * inv;

    if (live) out[row + h * B] = (float)n_h;
}

extern "C" void kernel_launch(void* const* d_in, const int* in_sizes, int n_in,
                              void* d_out, int out_size)
{
    const float* x    = (const float*)d_in[0];
    const float* a    = (const float*)d_in[1];
    const float* b    = (const float*)d_in[2];
    const float* mean = (const float*)d_in[3];
    const float* var  = (const float*)d_in[4];
    // d_in[5] = dim (always 1) — ignored.

    const int B = in_sizes[1];
    const int N = in_sizes[0] / B;

    nsab_reduce_kernel<<<B, THREADS>>>(x, a, b, N);
    nsab_solve_kernel<<<(2 * B + 63) / 64, 64>>>(mean, var, (float*)d_out, B, N);
}